// round 9
// baseline (speedup 1.0000x reference)
#include <cuda_runtime.h>
#include <cuda_bf16.h>

#define N_TOK 512
#define DIMC  1024
#define HEADS 16
#define DH    64
#define PP    32
#define PH    16   // P2

typedef unsigned long long ull;

// ---------------- scratch (device globals; no allocations allowed) -----------
__device__ float g_q[HEADS * N_TOK * DH];    // 2 MB
__device__ float g_k[HEADS * N_TOK * DH];    // 2 MB
__device__ float g_v[HEADS * N_TOK * DH];    // 2 MB
__device__ float g_a[HEADS * N_TOK * PP];    // 1 MB   a[h][n][p]
__device__ float g_c[HEADS * N_TOK * PP];    // 1 MB   c[h][n][p] (+b1 folded in)
__device__ float g_ctx[N_TOK * DIMC];        // 2 MB   attention output, [n][h*64+d]

// ---------------- f32x2 packed-FMA helpers (Blackwell) -----------------------
__device__ __forceinline__ ull pack2(float a, float b) {
    ull r; asm("mov.b64 %0, {%1,%2};" : "=l"(r) : "f"(a), "f"(b)); return r;
}
__device__ __forceinline__ ull fma2(ull a, ull b, ull c) {
    ull d; asm("fma.rn.f32x2 %0, %1, %2, %3;" : "=l"(d) : "l"(a), "l"(b), "l"(c)); return d;
}
__device__ __forceinline__ ull mul2(ull a, ull b) {
    ull d; asm("mul.rn.f32x2 %0, %1, %2;" : "=l"(d) : "l"(a), "l"(b)); return d;
}
__device__ __forceinline__ float2 unpack2(ull v) {
    float2 r; asm("mov.b64 {%0,%1}, %2;" : "=f"(r.x), "=f"(r.y) : "l"(v)); return r;
}

// =============================================================================
// K1 / K4 : fp32 GEMM  C[M][Nc] = A[M][K] * B[Nc][K]^T,  K = 1024, tiles 64x64
// MODE==1: A = x, B = Wqkv, epilogue scatters into g_q/g_k/g_v (head-major)
// MODE==0: A = g_ctx, B = Wout, epilogue stores C row-major (final output)
// =============================================================================
template <int MODE>
__global__ __launch_bounds__(256) void gemm_k(const float* __restrict__ Ain,
                                              const float* __restrict__ B,
                                              float* __restrict__ Cout)
{
    const float* A = MODE ? Ain : g_ctx;
    __shared__ __align__(16) float As[16][64];
    __shared__ __align__(16) float Bs[16][64];

    int t  = threadIdx.x;
    int tx = t & 15, ty = t >> 4;
    int m0 = blockIdx.y * 64, n0 = blockIdx.x * 64;
    int lr = t >> 2, lc = (t & 3) << 2;

    ull acc[4][2];
#pragma unroll
    for (int i = 0; i < 4; i++) { acc[i][0] = 0ULL; acc[i][1] = 0ULL; }

    const float* Aptr = A + (size_t)(m0 + lr) * DIMC + lc;
    const float* Bptr = B + (size_t)(n0 + lr) * DIMC + lc;

    for (int k0 = 0; k0 < DIMC; k0 += 16) {
        float4 av = *(const float4*)(Aptr + k0);
        float4 bv = *(const float4*)(Bptr + k0);
        As[lc + 0][lr] = av.x; As[lc + 1][lr] = av.y;
        As[lc + 2][lr] = av.z; As[lc + 3][lr] = av.w;
        Bs[lc + 0][lr] = bv.x; Bs[lc + 1][lr] = bv.y;
        Bs[lc + 2][lr] = bv.z; Bs[lc + 3][lr] = bv.w;
        __syncthreads();
#pragma unroll
        for (int kk = 0; kk < 16; kk++) {
            float4 a4 = *(const float4*)&As[kk][ty << 2];
            float4 b4 = *(const float4*)&Bs[kk][tx << 2];
            ull b01 = pack2(b4.x, b4.y), b23 = pack2(b4.z, b4.w);
            ull a0 = pack2(a4.x, a4.x), a1 = pack2(a4.y, a4.y);
            ull a2 = pack2(a4.z, a4.z), a3 = pack2(a4.w, a4.w);
            acc[0][0] = fma2(a0, b01, acc[0][0]); acc[0][1] = fma2(a0, b23, acc[0][1]);
            acc[1][0] = fma2(a1, b01, acc[1][0]); acc[1][1] = fma2(a1, b23, acc[1][1]);
            acc[2][0] = fma2(a2, b01, acc[2][0]); acc[2][1] = fma2(a2, b23, acc[2][1]);
            acc[3][0] = fma2(a3, b01, acc[3][0]); acc[3][1] = fma2(a3, b23, acc[3][1]);
        }
        __syncthreads();
    }

#pragma unroll
    for (int im = 0; im < 4; im++) {
        float2 c01 = unpack2(acc[im][0]);
        float2 c23 = unpack2(acc[im][1]);
        float vals[4] = {c01.x, c01.y, c23.x, c23.y};
        int m = m0 + (ty << 2) + im;
        if (MODE) {
            // o -> (d, s, h): o = d*48 + s*16 + h   (qkv.reshape(b,n,DH,3,HEADS))
#pragma unroll
            for (int io = 0; io < 4; io++) {
                int o  = n0 + (tx << 2) + io;
                int hh = o & 15;
                int s  = (o >> 4) % 3;
                int dd = o / 48;
                float* dst = (s == 0) ? g_q : (s == 1) ? g_k : g_v;
                dst[((hh * N_TOK) + m) * DH + dd] = vals[io];
            }
        } else {
            *(float4*)&Cout[(size_t)m * DIMC + n0 + (tx << 2)] =
                make_float4(vals[0], vals[1], vals[2], vals[3]);
        }
    }
}

// =============================================================================
// K2 : per-head projections.  z=0: a[h][n][q] = (q @ Wq^T + bq) @ W1q^T
//                             z=1: c[h][n][q] = (k @ Wk^T + bk) @ W1k^T + b1
// block = 64 tokens of one head; 256 threads (p-lane x 8 token-groups)
// =============================================================================
__global__ __launch_bounds__(256) void proj_k(const float* __restrict__ Wq_,
                                              const float* __restrict__ bq_,
                                              const float* __restrict__ Wk_,
                                              const float* __restrict__ bk_,
                                              const float* __restrict__ W1_,
                                              const float* __restrict__ b1_)
{
    __shared__ float Ws[PP][65];
    __shared__ float W1s[PP][33];
    __shared__ float qs[64][65];
    __shared__ float qps[64][33];
    __shared__ float bs[PP];
    __shared__ float b1s[PP];

    int t  = threadIdx.x;
    int z  = blockIdx.z, h = blockIdx.y, n0 = blockIdx.x * 64;
    const float* W    = z ? Wk_ : Wq_;
    const float* bias = z ? bk_ : bq_;
    const float* src  = z ? g_k : g_q;
    float*       dst  = z ? g_c : g_a;

    for (int idx = t; idx < PP * DH; idx += 256) { int p = idx >> 6, dd = idx & 63; Ws[p][dd] = W[idx]; }
    for (int idx = t; idx < PP * PP; idx += 256) { int q = idx >> 5, p = idx & 31; W1s[q][p] = W1_[q * (2 * PP) + z * PP + p]; }
    if (t < PP) { bs[t] = bias[t]; b1s[t] = b1_[t]; }
    for (int idx = t; idx < 64 * DH; idx += 256) {
        int nl = idx >> 6, dd = idx & 63;
        qs[nl][dd] = src[((h * N_TOK) + n0 + nl) * DH + dd];
    }
    __syncthreads();

    int p = t & 31, g8 = t >> 5;
#pragma unroll
    for (int m = 0; m < 8; m++) {
        int nl = g8 * 8 + m;
        float s = bs[p];
#pragma unroll 8
        for (int dd = 0; dd < DH; dd++) s += qs[nl][dd] * Ws[p][dd];
        qps[nl][p] = s;
    }
    __syncthreads();
#pragma unroll
    for (int m = 0; m < 8; m++) {
        int nl = g8 * 8 + m;
        float s = z ? b1s[p] : 0.f;   // fold b1 into c so the hot loop skips it
#pragma unroll 8
        for (int pp = 0; pp < PP; pp++) s += qps[nl][pp] * W1s[p][pp];
        dst[((h * N_TOK) + n0 + nl) * PP + p] = s;
    }
}

// =============================================================================
// K3 : flash attention with MLP scores. block = (head h, 32 query rows).
// 256 threads. score(i,j) = b3 + W3 . relu( W2 . relu(a_i + c_j) + b2 )
// causal: only j-tiles up to diagonal; online softmax; PV in f32x2 j-pairs.
// =============================================================================
__global__ __launch_bounds__(256) void attn_k(const float* __restrict__ W2_,
                                              const float* __restrict__ b2_,
                                              const float* __restrict__ W3_,
                                              const float* __restrict__ b3_)
{
    __shared__ __align__(16) float as_[PP][33];   // as_[p][i_local]
    __shared__ __align__(16) float cs_[PP][33];   // cs_[p][j_local]
    __shared__ __align__(16) float Vs[32][65];    // Vs[j][d]
    __shared__ __align__(16) float Ss[32][36];    // scores / probs (stride 36: 8B-ok)
    __shared__ __align__(16) float W2c[PP][PH];   // W2c[p][q] (column-major W2)
    __shared__ float m_s[32], l_s[32], sc_s[32];

    int t  = threadIdx.x;
    int h  = blockIdx.y, ib = blockIdx.x;
    int i0 = ib * 32;

    for (int idx = t; idx < PH * PP; idx += 256) { int q = idx >> 5, p = idx & 31; W2c[p][q] = W2_[idx]; }
    for (int idx = t; idx < 32 * PP; idx += 256) {
        int ii = idx >> 5, p = idx & 31;
        as_[p][ii] = g_a[((h * N_TOK) + i0 + ii) * PP + p];
    }
    if (t < 32) { m_s[t] = -1e30f; l_s[t] = 0.f; }

    float w3r[PH];
#pragma unroll
    for (int q = 0; q < PH; q++) w3r[q] = W3_[q];
    ull b2p[8];
    {
        const ull* b2u = (const ull*)b2_;
#pragma unroll
        for (int qq = 0; qq < 8; qq++) b2p[qq] = b2u[qq];
    }
    float b3v = b3_[0];

    ull acc[8];
#pragma unroll
    for (int k = 0; k < 8; k++) acc[k] = 0ULL;

    int jc = t & 31, rbase = t >> 5;     // scoring: col jc, rows rbase+8r
    int dd = t & 63, prow = t >> 6;      // PV: col d, rows prow+4k

    for (int jt = 0; jt <= ib; jt++) {
        int j0 = jt * 32;
        __syncthreads();   // also covers initial smem loads on first iteration
        for (int idx = t; idx < 32 * PP; idx += 256) {
            int jj = idx >> 5, p = idx & 31;
            cs_[p][jj] = g_c[((h * N_TOK) + j0 + jj) * PP + p];
        }
        for (int idx = t; idx < 32 * DH; idx += 256) {
            int jj = idx >> 6, d2 = idx & 63;
            Vs[jj][d2] = g_v[((h * N_TOK) + j0 + jj) * DH + d2];
        }
        __syncthreads();

        // ---- scoring: 4 pairs/thread, stream over p, f32x2 over the 16 q's
        ull h2p[4][8];
#pragma unroll
        for (int r = 0; r < 4; r++)
#pragma unroll
            for (int qq = 0; qq < 8; qq++) h2p[r][qq] = b2p[qq];

#pragma unroll 4
        for (int p = 0; p < PP; p++) {
            float cj = cs_[p][jc];
            ull w2v[8];
            const ull* wrow = (const ull*)&W2c[p][0];
#pragma unroll
            for (int qq = 0; qq < 8; qq++) w2v[qq] = wrow[qq];
#pragma unroll
            for (int r = 0; r < 4; r++) {
                float h1 = fmaxf(as_[p][rbase + 8 * r] + cj, 0.f);
                ull h11 = pack2(h1, h1);
#pragma unroll
                for (int qq = 0; qq < 8; qq++) h2p[r][qq] = fma2(h11, w2v[qq], h2p[r][qq]);
            }
        }
#pragma unroll
        for (int r = 0; r < 4; r++) {
            float s = b3v;
#pragma unroll
            for (int qq = 0; qq < 8; qq++) {
                float2 hq = unpack2(h2p[r][qq]);
                s += w3r[2 * qq]     * fmaxf(hq.x, 0.f);
                s += w3r[2 * qq + 1] * fmaxf(hq.y, 0.f);
            }
            int irow = rbase + 8 * r;
            if (j0 + jc > i0 + irow) s = -1e30f;   // causal mask
            Ss[irow][jc] = s;
        }
        __syncthreads();

        // ---- online softmax: 8 threads per row (within-warp shuffles)
        {
            int row = t >> 3, c8 = t & 7;
            float mx = -1e30f;
#pragma unroll
            for (int u = 0; u < 4; u++) mx = fmaxf(mx, Ss[row][c8 * 4 + u]);
            mx = fmaxf(mx, __shfl_xor_sync(0xffffffffu, mx, 1));
            mx = fmaxf(mx, __shfl_xor_sync(0xffffffffu, mx, 2));
            mx = fmaxf(mx, __shfl_xor_sync(0xffffffffu, mx, 4));
            float mnew = fmaxf(m_s[row], mx);
            float sum = 0.f;
#pragma unroll
            for (int u = 0; u < 4; u++) {
                float e = __expf(Ss[row][c8 * 4 + u] - mnew);
                Ss[row][c8 * 4 + u] = e;
                sum += e;
            }
            sum += __shfl_xor_sync(0xffffffffu, sum, 1);
            sum += __shfl_xor_sync(0xffffffffu, sum, 2);
            sum += __shfl_xor_sync(0xffffffffu, sum, 4);
            if (c8 == 0) {
                float scl = __expf(m_s[row] - mnew);   // first tile: exp(-1e30-m)=0
                sc_s[row] = scl;
                l_s[row]  = l_s[row] * scl + sum;
                m_s[row]  = mnew;
            }
        }
        __syncthreads();

        // ---- rescale + P@V (f32x2 pairs over j; horizontal add at the end)
#pragma unroll
        for (int k = 0; k < 8; k++) {
            float scl = sc_s[prow + 4 * k];
            acc[k] = mul2(acc[k], pack2(scl, scl));
        }
#pragma unroll 8
        for (int j = 0; j < 32; j += 2) {
            ull v2 = pack2(Vs[j][dd], Vs[j + 1][dd]);
#pragma unroll
            for (int k = 0; k < 8; k++) {
                int ir = prow + 4 * k;
                ull pj = *(const ull*)&Ss[ir][j];   // 8B-aligned: stride 36, j even
                acc[k] = fma2(pj, v2, acc[k]);
            }
        }
    }

    __syncthreads();
#pragma unroll
    for (int k = 0; k < 8; k++) {
        int ir = prow + 4 * k;
        float2 a2 = unpack2(acc[k]);
        float o = __fdividef(a2.x + a2.y, l_s[ir]);
        g_ctx[(size_t)(i0 + ir) * DIMC + h * DH + dd] = o;
    }
}

// =============================================================================
extern "C" void kernel_launch(void* const* d_in, const int* in_sizes, int n_in,
                              void* d_out, int out_size)
{
    const float* x    = (const float*)d_in[0];
    const float* Wqkv = (const float*)d_in[1];
    const float* Wout = (const float*)d_in[2];
    const float* Wq   = (const float*)d_in[3];
    const float* bq   = (const float*)d_in[4];
    const float* Wk   = (const float*)d_in[5];
    const float* bk   = (const float*)d_in[6];
    const float* W1   = (const float*)d_in[7];
    const float* b1   = (const float*)d_in[8];
    const float* W2   = (const float*)d_in[9];
    const float* b2   = (const float*)d_in[10];
    const float* W3   = (const float*)d_in[11];
    const float* b3   = (const float*)d_in[12];
    float* out = (float*)d_out;

    // K1: qkv = x @ Wqkv^T  -> scatter to g_q/g_k/g_v     (512 x 1024 x 3072)
    gemm_k<1><<<dim3(48, 8), 256>>>(x, Wqkv, nullptr);
    // K2: a = (qWq^T+bq)W1q^T ; c = (kWk^T+bk)W1k^T + b1
    proj_k<<<dim3(8, 16, 2), 256>>>(Wq, bq, Wk, bk, W1, b1);
    // K3: MLP-scored causal flash attention -> g_ctx
    attn_k<<<dim3(16, 16), 256>>>(W2, b2, W3, b3);
    // K4: y = g_ctx @ Wout^T                              (512 x 1024 x 1024)
    gemm_k<0><<<dim3(16, 8), 256>>>(nullptr, Wout, out);
}